// round 15
// baseline (speedup 1.0000x reference)
#include <cuda_runtime.h>
#include <cuda_bf16.h>
#include <cstdint>

#define DIMN 128
#define KEXT 144                        // 128 data + 4 norm-ext + 12 zero
#define KROW_B 288                      // bytes of data per extended row
#define NB   16384
#define NN   20000
#define NTX  256                        // 64-wide col tiles
#define NTILES2 16512                   // sum over by of (256 - 2*by)
#define EPSL 1e-6f
#define L2E  1.4426950408889634f
#define GRID_NL 296                     // 2 CTAs per SM
#define CHUNK ((NTILES2 + GRID_NL - 1) / GRID_NL)   // 56
#define LINK_GRID 2048
#define DONE_TOTAL (GRID_NL + LINK_GRID)
#define PREPB 5000                      // prep blocks in merged prep+gather

// smem geometry: extended rows padded to 304 B (odd multiple of 16 -> conflict-free ldsm)
#define ROWB 304
#define TILEB_A (128 * ROWB)            // 38912
#define TILEB_B (64 * ROWB)             // 19456
#define RING_OFF (TILEB_A + 2 * TILEB_B)        // 77824; 3 x 256B col-beta slices
#define BSA_OFF (RING_OFF + 3 * 256)            // 78592; 512B row-beta slice
#define DYN_SMEM_NL (BSA_OFF + 512)             // 79104 B -> 2 CTAs/SM

// ---- scratch (static device globals; no allocation) ----
__device__ __align__(16) __nv_bfloat16 g_p_bf[NN * DIMN];     // full p table (link)
__device__ __align__(16) __nv_bfloat16 g_pstar_bf[NN * DIMN]; // full p_star table (link)
__device__ __align__(16) __nv_bfloat16 g_psx_bf[NB * KEXT];   // A rows: [2*L2E*ps, -1,-1,-nsh,-nsl, 0..]
__device__ __align__(16) __nv_bfloat16 g_ppx_bf[NB * KEXT];   // B rows: [L2E*pp, nph,npl, 1,1, 0..]
__device__ float    g_bsA[NB];         // L2E * beta_p_star[nodes_p_star]
__device__ float    g_bsB[NB];         // L2E * beta_p[nodes_p]
__device__ int      g_done;            // finished-CTA counter (link + nonlink)
__device__ double   g_acc[2];          // [0]=link, [1]=nonlink

static __device__ __forceinline__ float sqrt_approx(float x) {
    float r; asm("sqrt.approx.f32 %0, %1;" : "=f"(r) : "f"(x)); return r;
}
static __device__ __forceinline__ float ex2_approx(float x) {
    float r; asm("ex2.approx.f32 %0, %1;" : "=f"(r) : "f"(x)); return r;
}
static __device__ __forceinline__ uint32_t smem_u32(const void* p) {
    uint32_t a;
    asm("{ .reg .u64 t; cvta.to.shared.u64 t, %1; cvt.u32.u64 %0, t; }" : "=r"(a) : "l"(p));
    return a;
}
static __device__ __forceinline__ void cp_async16(uint32_t dst, const void* src) {
    asm volatile("cp.async.cg.shared.global [%0], [%1], 16;" :: "r"(dst), "l"(src) : "memory");
}
static __device__ __forceinline__ void cp_commit() {
    asm volatile("cp.async.commit_group;" ::: "memory");
}
template <int N> static __device__ __forceinline__ void cp_wait() {
    asm volatile("cp.async.wait_group %0;" :: "n"(N) : "memory");
}
static __device__ __forceinline__ void ldsm_x4(uint32_t& r0, uint32_t& r1,
                                               uint32_t& r2, uint32_t& r3, uint32_t a) {
    asm volatile("ldmatrix.sync.aligned.m8n8.x4.shared.b16 {%0,%1,%2,%3}, [%4];"
                 : "=r"(r0), "=r"(r1), "=r"(r2), "=r"(r3) : "r"(a));
}
static __device__ __forceinline__ void mma16816(float* d, const uint32_t* a,
                                                uint32_t b0, uint32_t b1) {
    asm volatile("mma.sync.aligned.m16n8k16.row.col.f32.bf16.bf16.f32 "
                 "{%0,%1,%2,%3}, {%4,%5,%6,%7}, {%8,%9}, {%0,%1,%2,%3};"
                 : "+f"(d[0]), "+f"(d[1]), "+f"(d[2]), "+f"(d[3])
                 : "r"(a[0]), "r"(a[1]), "r"(a[2]), "r"(a[3]), "r"(b0), "r"(b1));
}
static __device__ __forceinline__ float2 bf2f(uint32_t u) {
    __nv_bfloat162 h = *reinterpret_cast<__nv_bfloat162*>(&u);
    return __bfloat1622float2(h);
}

// last-finisher writes the output (replaces a k_final launch)
static __device__ __forceinline__ void finish_and_maybe_write(float* out) {
    __threadfence();
    const int d = atomicAdd(&g_done, 1);
    if (d == DONE_TOTAL - 1) {
        __threadfence();
        out[0] = (float)(g_acc[1] - g_acc[0]);   // -(link - nonlink)
    }
}

// One epilogue slice: 4 elements. acc already holds -sq (norms folded into GEMM),
// so each element is just ex2(bsum - sqrt(|acc|)).
static __device__ __forceinline__ void epi_slice(
    float& nls, const float* d, float bs0, float bs1,
    const float* cv, bool diag, int r_lo, int c0) {
    const float cb0 = cv[0];
    const float cb1 = cv[1];
    if (!diag) {
        nls += ex2_approx(bs0 + cb0 - sqrt_approx(fabsf(d[0])));
        nls += ex2_approx(bs0 + cb1 - sqrt_approx(fabsf(d[1])));
        nls += ex2_approx(bs1 + cb0 - sqrt_approx(fabsf(d[2])));
        nls += ex2_approx(bs1 + cb1 - sqrt_approx(fabsf(d[3])));
    } else {
        float w;
        w = ex2_approx(bs0 + cb0 - sqrt_approx(fabsf(d[0])));
        if (r_lo < c0) nls += w;
        w = ex2_approx(bs0 + cb1 - sqrt_approx(fabsf(d[1])));
        if (r_lo < c0 + 1) nls += w;
        w = ex2_approx(bs1 + cb0 - sqrt_approx(fabsf(d[2])));
        if (r_lo + 8 < c0) nls += w;
        w = ex2_approx(bs1 + cb1 - sqrt_approx(fabsf(d[3])));
        if (r_lo + 8 < c0 + 1) nls += w;
    }
}

// ---------------- kernels ----------------
// Merged prep + gather.
// Blocks [0, PREPB): fp32 tables -> bf16 tables (for link kernel).
// Blocks [PREPB, ...): build extended GEMM rows + norm limbs + beta arrays.
__global__ void k_prep_gather(const float* __restrict__ p, const float* __restrict__ pstar,
                              const int* __restrict__ nps, const int* __restrict__ npp,
                              const float* __restrict__ beta_p, const float* __restrict__ beta_ps) {
    if (blockIdx.x == 0 && threadIdx.x == 0) {
        g_acc[0] = 0.0; g_acc[1] = 0.0; g_done = 0;
    }
    const int lane = threadIdx.x & 31;
    const int wloc = threadIdx.x >> 5;

    if (blockIdx.x < PREPB) {
        const int w   = blockIdx.x * 8 + wloc;
        const int row = w >> 1;
        if (row >= NN) return;
        const float* src = (w & 1) ? pstar : p;
        __nv_bfloat16* dst = (w & 1) ? g_pstar_bf : g_p_bf;
        float4 v = ((const float4*)(src + (size_t)row * DIMN))[lane];
        __nv_bfloat162* d = (__nv_bfloat162*)(dst + (size_t)row * DIMN);
        d[2 * lane + 0] = __floats2bfloat162_rn(v.x, v.y);
        d[2 * lane + 1] = __floats2bfloat162_rn(v.z, v.w);
    } else {
        const int row = (blockIdx.x - PREPB) * 8 + wloc;   // < NB by construction
        const int is = nps[row], ip = npp[row];
        float4 vs = ((const float4*)(pstar + (size_t)is * DIMN))[lane];
        float4 vp = ((const float4*)(p     + (size_t)ip * DIMN))[lane];

        // A side: a = bf16(L2E*ps); store 2a (exact doubling); norm from a
        __nv_bfloat162 a01 = __floats2bfloat162_rn(vs.x * L2E, vs.y * L2E);
        __nv_bfloat162 a23 = __floats2bfloat162_rn(vs.z * L2E, vs.w * L2E);
        float2 fa0 = __bfloat1622float2(a01), fa1 = __bfloat1622float2(a23);
        __nv_bfloat162* da = (__nv_bfloat162*)(g_psx_bf + (size_t)row * KEXT);
        da[2 * lane + 0] = __floats2bfloat162_rn(fa0.x * 2.f, fa0.y * 2.f);
        da[2 * lane + 1] = __floats2bfloat162_rn(fa1.x * 2.f, fa1.y * 2.f);

        // B side: b = bf16(L2E*pp); store as-is; norm from b
        __nv_bfloat162 b01 = __floats2bfloat162_rn(vp.x * L2E, vp.y * L2E);
        __nv_bfloat162 b23 = __floats2bfloat162_rn(vp.z * L2E, vp.w * L2E);
        float2 fb0 = __bfloat1622float2(b01), fb1 = __bfloat1622float2(b23);
        __nv_bfloat162* db = (__nv_bfloat162*)(g_ppx_bf + (size_t)row * KEXT);
        db[2 * lane + 0] = b01;
        db[2 * lane + 1] = b23;

        float a = fa0.x*fa0.x + fa0.y*fa0.y + fa1.x*fa1.x + fa1.y*fa1.y;
        float b = fb0.x*fb0.x + fb0.y*fb0.y + fb1.x*fb1.x + fb1.y*fb1.y;
#pragma unroll
        for (int o = 16; o; o >>= 1) {
            a += __shfl_xor_sync(0xffffffffu, a, o);
            b += __shfl_xor_sync(0xffffffffu, b, o);
        }
        if (lane == 0) {
            // norm limbs (hi + lo) -> ~1e-3 absolute norm error
            const float ns = a, np = b;
            __nv_bfloat16 nsh = __float2bfloat16(ns);
            __nv_bfloat16 nsl = __float2bfloat16(ns - __bfloat162float(nsh));
            __nv_bfloat16 nph = __float2bfloat16(np);
            __nv_bfloat16 npl = __float2bfloat16(np - __bfloat162float(nph));
            const __nv_bfloat16 zero = __float2bfloat16(0.f);
            const __nv_bfloat16 one  = __float2bfloat16(1.f);
            const __nv_bfloat16 m1   = __float2bfloat16(-1.f);
            __nv_bfloat16* ea = g_psx_bf + (size_t)row * KEXT + 128;
            __nv_bfloat16* eb = g_ppx_bf + (size_t)row * KEXT + 128;
            ea[0] = m1; ea[1] = m1;
            ea[2] = __float2bfloat16(-__bfloat162float(nsh));
            ea[3] = __float2bfloat16(-__bfloat162float(nsl));
            eb[0] = nph; eb[1] = npl; eb[2] = one; eb[3] = one;
#pragma unroll
            for (int i = 4; i < 16; i++) { ea[i] = zero; eb[i] = zero; }
            g_bsA[row] = beta_ps[is] * L2E;
            g_bsB[row] = beta_p[ip] * L2E;
        }
    }
}

// Link term: 8 lanes per edge, 4 edges per warp in parallel (3-deep shfl reduce).
__global__ void k_link(const int* __restrict__ edges, int E,
                       const float* __restrict__ beta_p, const float* __restrict__ beta_ps,
                       float* __restrict__ out) {
    __shared__ float wsum[8];
    const int gw   = (blockIdx.x * blockDim.x + threadIdx.x) >> 5;
    const int wid  = threadIdx.x >> 5;
    const int lane = threadIdx.x & 31;
    const int nw   = (gridDim.x * blockDim.x) >> 5;
    const int sub  = lane & 7;
    const int eq   = lane >> 3;

    float local = 0.f;
    for (int base = gw * 4; base < E; base += nw * 4) {
        const int e = base + eq;
        const bool valid = (e < E);
        float s = 0.f;
        int e0 = 0, e1 = 0;
        if (valid) {
            e0 = edges[e]; e1 = edges[E + e];
            const uint4* ra = (const uint4*)(g_p_bf     + (size_t)e0 * DIMN);
            const uint4* rb = (const uint4*)(g_pstar_bf + (size_t)e1 * DIMN);
            const uint4 a0 = ra[2 * sub], a1 = ra[2 * sub + 1];
            const uint4 b0 = rb[2 * sub], b1 = rb[2 * sub + 1];
#pragma unroll
            for (int w = 0; w < 4; w++) {
                const float2 fa = bf2f((&a0.x)[w]), fb = bf2f((&b0.x)[w]);
                const float dx = fa.x - fb.x + EPSL, dy = fa.y - fb.y + EPSL;
                s += dx * dx + dy * dy;
            }
#pragma unroll
            for (int w = 0; w < 4; w++) {
                const float2 fa = bf2f((&a1.x)[w]), fb = bf2f((&b1.x)[w]);
                const float dx = fa.x - fb.x + EPSL, dy = fa.y - fb.y + EPSL;
                s += dx * dx + dy * dy;
            }
        }
        s += __shfl_xor_sync(0xffffffffu, s, 1);
        s += __shfl_xor_sync(0xffffffffu, s, 2);
        s += __shfl_xor_sync(0xffffffffu, s, 4);
        if (valid && sub == 0)
            local += beta_ps[e0] + beta_p[e1] - sqrt_approx(s);
    }
#pragma unroll
    for (int o = 16; o; o >>= 1) local += __shfl_xor_sync(0xffffffffu, local, o);
    if (lane == 0) wsum[wid] = local;
    __syncthreads();
    if (threadIdx.x == 0) {
        float s = 0.f;
#pragma unroll
        for (int w = 0; w < 8; w++) s += wsum[w];
        atomicAdd(&g_acc[0], (double)s);
        finish_and_maybe_write(out);
    }
}

// Non-link: persistent mma.sync bf16 GEMM over 128x64 triu tiles with NORMS
// FOLDED INTO K (K=144): acc = 2g - ns - np = -sq, so the epilogue is just
// ex2(bsum - sqrt(|acc|)). 8 warps x 32x32; A persists across same-row tiles;
// B double-buffered; beta vectors staged in smem. 2 CTAs/SM.
__global__ __launch_bounds__(256, 2)
void k_nonlink_mma(float* __restrict__ out) {
    extern __shared__ __align__(16) char smem[];
    __shared__ float warpsum[8];
    const int tid  = threadIdx.x;
    const int wid  = tid >> 5;
    const int lane = tid & 31;
    const uint32_t sbase = smem_u32(smem);
    const uint32_t abase = sbase;
    const uint32_t bst[2] = { sbase + TILEB_A, sbase + TILEB_A + TILEB_B };
    const float* const s_ring = (const float*)(smem + RING_OFF);   // 3 x 64 floats
    const float* const s_bsA  = (const float*)(smem + BSA_OFF);    // 128 floats

    const int row0w = (wid & 3) * 32;     // 4 M-strips of 32
    const int col0w = (wid >> 2) * 32;    // 2 N-strips of 32
    const uint32_t lm_off = (uint32_t)(lane & 15) * ROWB + (uint32_t)(lane >> 4) * 16;
    const int lq = 2 * (lane & 3);
    const int lr = lane >> 2;

    float nls = 0.f;

    const int t0 = blockIdx.x * CHUNK;
    const int t1 = (t0 + CHUNK < NTILES2) ? (t0 + CHUNK) : NTILES2;

    if (t0 < t1) {
        // decode t0 -> (by, bx): row by has NTX - 2*by tiles, bx in [2*by, NTX)
        int by = 0, rem = t0;
        while (rem >= NTX - 2 * by) { rem -= NTX - 2 * by; by++; }
        int bx = 2 * by + rem;
        int slot = 0;

        // prologue: A(by) + bsA(by) + B(bx) + colbeta(bx)
#pragma unroll
        for (int it = 0; it < 9; it++) {      // 128 rows x 18 chunks = 2304
            const int c = tid + (it << 8);
            const int m = c / 18, q = c - m * 18;
            cp_async16(abase + (uint32_t)m * ROWB + (uint32_t)q * 16,
                       (const char*)g_psx_bf + (size_t)((by << 7) + m) * KROW_B + ((size_t)q << 4));
        }
#pragma unroll
        for (int it = 0; it < 5; it++) {      // 64 rows x 18 chunks = 1152
            const int c = tid + (it << 8);
            if (c < 1152) {
                const int m = c / 18, q = c - m * 18;
                cp_async16(bst[0] + (uint32_t)m * ROWB + (uint32_t)q * 16,
                           (const char*)g_ppx_bf + (size_t)((bx << 6) + m) * KROW_B + ((size_t)q << 4));
            }
        }
        if (tid < 16)
            cp_async16(sbase + RING_OFF + (uint32_t)tid * 16,
                       (const char*)g_bsB + ((size_t)bx << 8) + ((size_t)tid << 4));
        else if (tid < 48)
            cp_async16(sbase + BSA_OFF + (uint32_t)(tid - 16) * 16,
                       (const char*)g_bsA + ((size_t)by << 9) + ((size_t)(tid - 16) << 4));
        cp_commit();

        int s = 0;
        for (int t = t0; t < t1; t++) {
            int nbx = bx + 1, nby = by;
            if (nbx >= NTX) { nby = by + 1; nbx = 2 * nby; }
            const int nslot = (slot + 1 == 3) ? 0 : slot + 1;
            const bool have_next = (t + 1 < t1);

            if (have_next) {
#pragma unroll
                for (int it = 0; it < 5; it++) {
                    const int c = tid + (it << 8);
                    if (c < 1152) {
                        const int m = c / 18, q = c - m * 18;
                        cp_async16(bst[1 - s] + (uint32_t)m * ROWB + (uint32_t)q * 16,
                                   (const char*)g_ppx_bf + (size_t)((nbx << 6) + m) * KROW_B + ((size_t)q << 4));
                    }
                }
                if (tid < 16)
                    cp_async16(sbase + RING_OFF + (uint32_t)nslot * 256 + (uint32_t)tid * 16,
                               (const char*)g_bsB + ((size_t)nbx << 8) + ((size_t)tid << 4));
            }
            cp_commit();
            cp_wait<1>();
            __syncthreads();

            const uint32_t aw = abase  + (uint32_t)row0w * ROWB + lm_off;
            const uint32_t bw = bst[s] + (uint32_t)col0w * ROWB + lm_off;

            float acc[2][4][4];
#pragma unroll
            for (int mi = 0; mi < 2; mi++)
#pragma unroll
                for (int n = 0; n < 4; n++)
#pragma unroll
                    for (int v = 0; v < 4; v++) acc[mi][n][v] = 0.f;

#pragma unroll
            for (int k = 0; k < 9; k++) {     // K = 144
                uint32_t a[2][4], bf[2][4];
#pragma unroll
                for (int mi = 0; mi < 2; mi++)
                    ldsm_x4(a[mi][0], a[mi][1], a[mi][2], a[mi][3],
                            aw + (uint32_t)mi * 16 * ROWB + (uint32_t)k * 32);
#pragma unroll
                for (int nj = 0; nj < 2; nj++)
                    ldsm_x4(bf[nj][0], bf[nj][1], bf[nj][2], bf[nj][3],
                            bw + (uint32_t)nj * 16 * ROWB + (uint32_t)k * 32);
#pragma unroll
                for (int mi = 0; mi < 2; mi++)
#pragma unroll
                    for (int n = 0; n < 4; n++) {
                        const int nj = n >> 1;
                        if ((n & 1) == 0) mma16816(acc[mi][n], a[mi], bf[nj][0], bf[nj][2]);
                        else              mma16816(acc[mi][n], a[mi], bf[nj][1], bf[nj][3]);
                    }
            }

            // epilogue: acc = -sq; w = ex2(bsum - sqrt(|acc|))
            {
                const int crl = (by << 7) + row0w + lr;
                const float rb0 = s_bsA[row0w + lr];
                const float rb1 = s_bsA[row0w + lr + 8];
                const float rb2 = s_bsA[row0w + lr + 16];
                const float rb3 = s_bsA[row0w + lr + 24];
                const float* const cbet = s_ring + slot * 64;
                const int cb = (bx << 6) + col0w + lq;
                const bool diag = ((bx >> 1) == by);
#pragma unroll
                for (int n = 0; n < 4; n++) {
                    epi_slice(nls, acc[0][n], rb0, rb1,
                              cbet + col0w + lq + n * 8, diag, crl, cb + n * 8);
                    epi_slice(nls, acc[1][n], rb2, rb3,
                              cbet + col0w + lq + n * 8, diag, crl + 16, cb + n * 8);
                }
            }
            __syncthreads();    // done with A, B stage s, ring slot, bsA

            if (have_next && nby != by) {   // A + bsA refill for next row
#pragma unroll
                for (int it = 0; it < 9; it++) {
                    const int c = tid + (it << 8);
                    const int m = c / 18, q = c - m * 18;
                    cp_async16(abase + (uint32_t)m * ROWB + (uint32_t)q * 16,
                               (const char*)g_psx_bf + (size_t)((nby << 7) + m) * KROW_B + ((size_t)q << 4));
                }
                if (tid < 32)
                    cp_async16(sbase + BSA_OFF + (uint32_t)tid * 16,
                               (const char*)g_bsA + ((size_t)nby << 9) + ((size_t)tid << 4));
                cp_commit();
            }

            by = nby; bx = nbx; s ^= 1; slot = nslot;
        }
    }

#pragma unroll
    for (int o = 16; o; o >>= 1) nls += __shfl_xor_sync(0xffffffffu, nls, o);
    if (lane == 0) warpsum[wid] = nls;
    __syncthreads();
    if (tid == 0) {
        float sum = 0.f;
#pragma unroll
        for (int w = 0; w < 8; w++) sum += warpsum[w];
        atomicAdd(&g_acc[1], (double)sum);
        finish_and_maybe_write(out);
    }
}

extern "C" void kernel_launch(void* const* d_in, const int* in_sizes, int n_in,
                              void* d_out, int out_size) {
    const int*   edges   = (const int*)d_in[0];
    const int*   nps     = (const int*)d_in[1];   // nodes_p_star
    const int*   npp     = (const int*)d_in[2];   // nodes_p
    const float* beta_p  = (const float*)d_in[3];
    const float* beta_ps = (const float*)d_in[4];
    const float* p       = (const float*)d_in[5];
    const float* pstar   = (const float*)d_in[6];
    float* out = (float*)d_out;
    int E = in_sizes[0] / 2;

    cudaFuncSetAttribute(k_nonlink_mma, cudaFuncAttributeMaxDynamicSharedMemorySize, DYN_SMEM_NL);

    k_prep_gather<<<PREPB + NB / 8, 256>>>(p, pstar, nps, npp, beta_p, beta_ps);
    k_link<<<LINK_GRID, 256>>>(edges, E, beta_p, beta_ps, out);
    k_nonlink_mma<<<GRID_NL, 256, DYN_SMEM_NL>>>(out);
}

// round 16
// speedup vs baseline: 1.5861x; 1.5861x over previous
#include <cuda_runtime.h>
#include <cuda_bf16.h>
#include <cstdint>

#define DIMN 128
#define NB   16384
#define NN   20000
#define NTX  256                        // 64-wide col tiles
#define NTILES2 16512                   // sum over by of (256 - 2*by)
#define EPSL 1e-6f
#define L2E  1.4426950408889634f
#define GRID_NL 444                     // 3 CTAs per SM
#define CHUNK ((NTILES2 + GRID_NL - 1) / GRID_NL)   // 38

// smem geometry: rows padded to 272 B (136 bf16)
#define ROWB 272
#define TILEB_A (128 * ROWB)            // 34816
#define TILEB_B (64 * ROWB)             // 17408
#define RING_OFF (TILEB_A + 2 * TILEB_B)        // 69632; 3 x 512B npbp slices
#define NSBS_OFF (RING_OFF + 3 * 512)           // 71168; 1KB nsbs row slice
#define DYN_SMEM_NL (NSBS_OFF + 1024)           // 72192 B -> 3 CTAs/SM

// ---- scratch (static device globals; no allocation) ----
__device__ __align__(16) __nv_bfloat16 g_p_bf[NN * DIMN];     // full p table, bf16
__device__ __align__(16) __nv_bfloat16 g_pstar_bf[NN * DIMN]; // full p_star table, bf16
__device__ __align__(16) __nv_bfloat16 g_ps_bf[NB * DIMN];    // L2E * p_star[nodes_p_star]
__device__ __align__(16) __nv_bfloat16 g_pp_bf[NB * DIMN];    // L2E * p[nodes_p]
__device__ float2   g_nsbs[NB];        // {|scaled ps row|^2, L2E*beta_p_star}
__device__ float2   g_npbp[NB];        // {|scaled pp row|^2, L2E*beta_p}
__device__ double   g_acc[2];          // [0]=link, [1]=nonlink

static __device__ __forceinline__ float sqrt_approx(float x) {
    float r; asm("sqrt.approx.f32 %0, %1;" : "=f"(r) : "f"(x)); return r;
}
static __device__ __forceinline__ float ex2_approx(float x) {
    float r; asm("ex2.approx.f32 %0, %1;" : "=f"(r) : "f"(x)); return r;
}
static __device__ __forceinline__ uint32_t smem_u32(const void* p) {
    uint32_t a;
    asm("{ .reg .u64 t; cvta.to.shared.u64 t, %1; cvt.u32.u64 %0, t; }" : "=r"(a) : "l"(p));
    return a;
}
static __device__ __forceinline__ void cp_async16(uint32_t dst, const void* src) {
    asm volatile("cp.async.cg.shared.global [%0], [%1], 16;" :: "r"(dst), "l"(src) : "memory");
}
static __device__ __forceinline__ void cp_commit() {
    asm volatile("cp.async.commit_group;" ::: "memory");
}
template <int N> static __device__ __forceinline__ void cp_wait() {
    asm volatile("cp.async.wait_group %0;" :: "n"(N) : "memory");
}
static __device__ __forceinline__ void ldsm_x4(uint32_t& r0, uint32_t& r1,
                                               uint32_t& r2, uint32_t& r3, uint32_t a) {
    asm volatile("ldmatrix.sync.aligned.m8n8.x4.shared.b16 {%0,%1,%2,%3}, [%4];"
                 : "=r"(r0), "=r"(r1), "=r"(r2), "=r"(r3) : "r"(a));
}
static __device__ __forceinline__ void mma16816(float* d, const uint32_t* a,
                                                uint32_t b0, uint32_t b1) {
    asm volatile("mma.sync.aligned.m16n8k16.row.col.f32.bf16.bf16.f32 "
                 "{%0,%1,%2,%3}, {%4,%5,%6,%7}, {%8,%9}, {%0,%1,%2,%3};"
                 : "+f"(d[0]), "+f"(d[1]), "+f"(d[2]), "+f"(d[3])
                 : "r"(a[0]), "r"(a[1]), "r"(a[2]), "r"(a[3]), "r"(b0), "r"(b1));
}
static __device__ __forceinline__ float2 bf2f(uint32_t u) {
    __nv_bfloat162 h = *reinterpret_cast<__nv_bfloat162*>(&u);
    return __bfloat1622float2(h);
}

// One epilogue slice: 4 elements (rows r_lo, r_lo+8 x cols c0, c0+1).
// cv pairs come from an smem-staged slice (LDS).
static __device__ __forceinline__ void epi_slice(
    float& nls, const float* d, const float2 rv0, const float2 rv1,
    const float2* cvp, bool diag, int r_lo, int c0) {
    const float2 cv0 = cvp[0];
    const float2 cv1 = cvp[1];
    if (!diag) {
        nls += ex2_approx(rv0.y + cv0.y - sqrt_approx(fmaxf(rv0.x + cv0.x - 2.f * d[0], 0.f)));
        nls += ex2_approx(rv0.y + cv1.y - sqrt_approx(fmaxf(rv0.x + cv1.x - 2.f * d[1], 0.f)));
        nls += ex2_approx(rv1.y + cv0.y - sqrt_approx(fmaxf(rv1.x + cv0.x - 2.f * d[2], 0.f)));
        nls += ex2_approx(rv1.y + cv1.y - sqrt_approx(fmaxf(rv1.x + cv1.x - 2.f * d[3], 0.f)));
    } else {
        float w;
        w = ex2_approx(rv0.y + cv0.y - sqrt_approx(fmaxf(rv0.x + cv0.x - 2.f * d[0], 0.f)));
        if (r_lo < c0) nls += w;
        w = ex2_approx(rv0.y + cv1.y - sqrt_approx(fmaxf(rv0.x + cv1.x - 2.f * d[1], 0.f)));
        if (r_lo < c0 + 1) nls += w;
        w = ex2_approx(rv1.y + cv0.y - sqrt_approx(fmaxf(rv1.x + cv0.x - 2.f * d[2], 0.f)));
        if (r_lo + 8 < c0) nls += w;
        w = ex2_approx(rv1.y + cv1.y - sqrt_approx(fmaxf(rv1.x + cv1.x - 2.f * d[3], 0.f)));
        if (r_lo + 8 < c0 + 1) nls += w;
    }
}

// ---------------- kernels ----------------
// convert full p / p_star tables to bf16 (one warp per row per table); zero counters
__global__ void k_prep(const float* __restrict__ p, const float* __restrict__ pstar) {
    if (blockIdx.x == 0 && threadIdx.x == 0) { g_acc[0] = 0.0; g_acc[1] = 0.0; }
    int w    = blockIdx.x * 8 + (threadIdx.x >> 5);
    int lane = threadIdx.x & 31;
    int row  = w >> 1;
    if (row >= NN) return;
    const float* src = (w & 1) ? pstar : p;
    __nv_bfloat16* dst = (w & 1) ? g_pstar_bf : g_p_bf;
    float4 v = ((const float4*)(src + (size_t)row * DIMN))[lane];
    __nv_bfloat162* d = (__nv_bfloat162*)(dst + (size_t)row * DIMN);
    d[2 * lane + 0] = __floats2bfloat162_rn(v.x, v.y);
    d[2 * lane + 1] = __floats2bfloat162_rn(v.z, v.w);
}

// gather rows (from bf16 tables), scale by L2E, store scaled bf16 + {norm,beta} pairs
__global__ void k_gather(const int* __restrict__ nps, const int* __restrict__ npp,
                         const float* __restrict__ beta_p, const float* __restrict__ beta_ps) {
    int row  = blockIdx.x * 8 + (threadIdx.x >> 5);
    int lane = threadIdx.x & 31;
    if (row >= NB) return;
    int is = nps[row], ip = npp[row];
    uint2 rs = ((const uint2*)(g_pstar_bf + (size_t)is * DIMN))[lane];
    uint2 rp = ((const uint2*)(g_p_bf     + (size_t)ip * DIMN))[lane];

    float2 s0 = bf2f(rs.x), s1 = bf2f(rs.y), p0 = bf2f(rp.x), p1 = bf2f(rp.y);
    __nv_bfloat162 os0 = __floats2bfloat162_rn(s0.x * L2E, s0.y * L2E);
    __nv_bfloat162 os1 = __floats2bfloat162_rn(s1.x * L2E, s1.y * L2E);
    __nv_bfloat162 op0 = __floats2bfloat162_rn(p0.x * L2E, p0.y * L2E);
    __nv_bfloat162 op1 = __floats2bfloat162_rn(p1.x * L2E, p1.y * L2E);
    ((__nv_bfloat162*)(g_ps_bf + (size_t)row * DIMN))[2 * lane + 0] = os0;
    ((__nv_bfloat162*)(g_ps_bf + (size_t)row * DIMN))[2 * lane + 1] = os1;
    ((__nv_bfloat162*)(g_pp_bf + (size_t)row * DIMN))[2 * lane + 0] = op0;
    ((__nv_bfloat162*)(g_pp_bf + (size_t)row * DIMN))[2 * lane + 1] = op1;

    float2 a0 = __bfloat1622float2(os0), a1 = __bfloat1622float2(os1);
    float2 b0 = __bfloat1622float2(op0), b1 = __bfloat1622float2(op1);
    float a = a0.x*a0.x + a0.y*a0.y + a1.x*a1.x + a1.y*a1.y;
    float b = b0.x*b0.x + b0.y*b0.y + b1.x*b1.x + b1.y*b1.y;
#pragma unroll
    for (int o = 16; o; o >>= 1) {
        a += __shfl_xor_sync(0xffffffffu, a, o);
        b += __shfl_xor_sync(0xffffffffu, b, o);
    }
    if (lane == 0) {
        g_nsbs[row] = make_float2(a, beta_ps[is] * L2E);
        g_npbp[row] = make_float2(b, beta_p[ip] * L2E);
    }
}

// Link term: 8 lanes per edge, 4 edges per warp in parallel (3-deep shfl reduce).
__global__ void k_link(const int* __restrict__ edges, int E,
                       const float* __restrict__ beta_p, const float* __restrict__ beta_ps) {
    __shared__ float wsum[8];
    const int gw   = (blockIdx.x * blockDim.x + threadIdx.x) >> 5;
    const int wid  = threadIdx.x >> 5;
    const int lane = threadIdx.x & 31;
    const int nw   = (gridDim.x * blockDim.x) >> 5;
    const int sub  = lane & 7;
    const int eq   = lane >> 3;

    float local = 0.f;
    for (int base = gw * 4; base < E; base += nw * 4) {
        const int e = base + eq;
        const bool valid = (e < E);
        float s = 0.f;
        int e0 = 0, e1 = 0;
        if (valid) {
            e0 = edges[e]; e1 = edges[E + e];
            const uint4* ra = (const uint4*)(g_p_bf     + (size_t)e0 * DIMN);
            const uint4* rb = (const uint4*)(g_pstar_bf + (size_t)e1 * DIMN);
            const uint4 a0 = ra[2 * sub], a1 = ra[2 * sub + 1];
            const uint4 b0 = rb[2 * sub], b1 = rb[2 * sub + 1];
#pragma unroll
            for (int w = 0; w < 4; w++) {
                const float2 fa = bf2f((&a0.x)[w]), fb = bf2f((&b0.x)[w]);
                const float dx = fa.x - fb.x + EPSL, dy = fa.y - fb.y + EPSL;
                s += dx * dx + dy * dy;
            }
#pragma unroll
            for (int w = 0; w < 4; w++) {
                const float2 fa = bf2f((&a1.x)[w]), fb = bf2f((&b1.x)[w]);
                const float dx = fa.x - fb.x + EPSL, dy = fa.y - fb.y + EPSL;
                s += dx * dx + dy * dy;
            }
        }
        s += __shfl_xor_sync(0xffffffffu, s, 1);
        s += __shfl_xor_sync(0xffffffffu, s, 2);
        s += __shfl_xor_sync(0xffffffffu, s, 4);
        if (valid && sub == 0)
            local += beta_ps[e0] + beta_p[e1] - sqrt_approx(s);
    }
#pragma unroll
    for (int o = 16; o; o >>= 1) local += __shfl_xor_sync(0xffffffffu, local, o);
    if (lane == 0) wsum[wid] = local;
    __syncthreads();
    if (threadIdx.x == 0) {
        float s = 0.f;
#pragma unroll
        for (int w = 0; w < 8; w++) s += wsum[w];
        atomicAdd(&g_acc[0], (double)s);
    }
}

// Non-link: persistent mma.sync bf16 GEMM over 128x64 triu tiles, 3 CTAs/SM.
// 8 warps x 32x32 strips; A (128 rows) persists across same-row tiles;
// B (64 rows) double-buffered; epilogue vectors staged in smem (LDS only).
__global__ __launch_bounds__(256, 3)
void k_nonlink_mma() {
    extern __shared__ __align__(16) char smem[];
    __shared__ float warpsum[8];
    const int tid  = threadIdx.x;
    const int wid  = tid >> 5;
    const int lane = tid & 31;
    const uint32_t sbase = smem_u32(smem);
    const uint32_t abase = sbase;
    const uint32_t bst[2] = { sbase + TILEB_A, sbase + TILEB_A + TILEB_B };
    const float2* const s_ring = (const float2*)(smem + RING_OFF);   // 3 x 64 float2
    const float2* const s_ns   = (const float2*)(smem + NSBS_OFF);   // 128 float2

    const int row0w = (wid & 3) * 32;     // 4 M-strips of 32
    const int col0w = (wid >> 2) * 32;    // 2 N-strips of 32
    const uint32_t lm_off = (uint32_t)(lane & 15) * ROWB + (uint32_t)(lane >> 4) * 16;
    const int lq = 2 * (lane & 3);
    const int lr = lane >> 2;

    float nls = 0.f;

    const int t0 = blockIdx.x * CHUNK;
    const int t1 = (t0 + CHUNK < NTILES2) ? (t0 + CHUNK) : NTILES2;

    if (t0 < t1) {
        // decode t0 -> (by, bx): row by has NTX - 2*by tiles, bx in [2*by, NTX)
        int by = 0, rem = t0;
        while (rem >= NTX - 2 * by) { rem -= NTX - 2 * by; by++; }
        int bx = 2 * by + rem;
        int slot = 0;

        // prologue: A(by) + nsbs(by) + B(bx) + npbp(bx)
#pragma unroll
        for (int it = 0; it < 8; it++) {
            const int c = tid + (it << 8);
            const int m = c >> 4, q = c & 15;
            cp_async16(abase + (uint32_t)m * ROWB + (uint32_t)q * 16,
                       (const char*)g_ps_bf + ((size_t)((by << 7) + m) << 8) + ((size_t)q << 4));
        }
#pragma unroll
        for (int it = 0; it < 4; it++) {
            const int c = tid + (it << 8);
            const int m = c >> 4, q = c & 15;
            cp_async16(bst[0] + (uint32_t)m * ROWB + (uint32_t)q * 16,
                       (const char*)g_pp_bf + ((size_t)((bx << 6) + m) << 8) + ((size_t)q << 4));
        }
        if (tid < 32)
            cp_async16(sbase + RING_OFF + (uint32_t)tid * 16,
                       (const char*)g_npbp + ((size_t)bx << 9) + ((size_t)tid << 4));
        else if (tid < 96)
            cp_async16(sbase + NSBS_OFF + (uint32_t)(tid - 32) * 16,
                       (const char*)g_nsbs + ((size_t)by << 10) + ((size_t)(tid - 32) << 4));
        cp_commit();

        int s = 0;
        for (int t = t0; t < t1; t++) {
            int nbx = bx + 1, nby = by;
            if (nbx >= NTX) { nby = by + 1; nbx = 2 * nby; }
            const int nslot = (slot + 1 == 3) ? 0 : slot + 1;
            const bool have_next = (t + 1 < t1);

            if (have_next) {
#pragma unroll
                for (int it = 0; it < 4; it++) {
                    const int c = tid + (it << 8);
                    const int m = c >> 4, q = c & 15;
                    cp_async16(bst[1 - s] + (uint32_t)m * ROWB + (uint32_t)q * 16,
                               (const char*)g_pp_bf + ((size_t)((nbx << 6) + m) << 8) + ((size_t)q << 4));
                }
                if (tid < 32)
                    cp_async16(sbase + RING_OFF + (uint32_t)nslot * 512 + (uint32_t)tid * 16,
                               (const char*)g_npbp + ((size_t)nbx << 9) + ((size_t)tid << 4));
            }
            cp_commit();
            cp_wait<1>();
            __syncthreads();

            const uint32_t aw = abase  + (uint32_t)row0w * ROWB + lm_off;
            const uint32_t bw = bst[s] + (uint32_t)col0w * ROWB + lm_off;

            float acc[2][4][4];
#pragma unroll
            for (int mi = 0; mi < 2; mi++)
#pragma unroll
                for (int n = 0; n < 4; n++)
#pragma unroll
                    for (int v = 0; v < 4; v++) acc[mi][n][v] = 0.f;

#pragma unroll
            for (int k = 0; k < 8; k++) {
                uint32_t a[2][4], bf[2][4];
#pragma unroll
                for (int mi = 0; mi < 2; mi++)
                    ldsm_x4(a[mi][0], a[mi][1], a[mi][2], a[mi][3],
                            aw + (uint32_t)mi * 16 * ROWB + (uint32_t)k * 32);
#pragma unroll
                for (int nj = 0; nj < 2; nj++)
                    ldsm_x4(bf[nj][0], bf[nj][1], bf[nj][2], bf[nj][3],
                            bw + (uint32_t)nj * 16 * ROWB + (uint32_t)k * 32);
#pragma unroll
                for (int mi = 0; mi < 2; mi++)
#pragma unroll
                    for (int n = 0; n < 4; n++) {
                        const int nj = n >> 1;
                        if ((n & 1) == 0) mma16816(acc[mi][n], a[mi], bf[nj][0], bf[nj][2]);
                        else              mma16816(acc[mi][n], a[mi], bf[nj][1], bf[nj][3]);
                    }
            }

            // batched epilogue (LDS-staged vectors; values pre-scaled by L2E)
            {
                const int crl = (by << 7) + row0w + lr;
                float2 rv[4];
                rv[0] = s_ns[row0w + lr];      rv[1] = s_ns[row0w + lr + 8];
                rv[2] = s_ns[row0w + lr + 16]; rv[3] = s_ns[row0w + lr + 24];
                const float2* const cnp = s_ring + slot * 64;
                const int cb = (bx << 6) + col0w + lq;
                const bool diag = ((bx >> 1) == by);
#pragma unroll
                for (int mi = 0; mi < 2; mi++)
#pragma unroll
                    for (int n = 0; n < 4; n++)
                        epi_slice(nls, acc[mi][n], rv[mi * 2], rv[mi * 2 + 1],
                                  cnp + col0w + lq + n * 8, diag,
                                  crl + mi * 16, cb + n * 8);
            }
            __syncthreads();    // done with A, B stage s, ring slot, nsbs

            if (have_next && nby != by) {   // A + nsbs refill for next row
#pragma unroll
                for (int it = 0; it < 8; it++) {
                    const int c = tid + (it << 8);
                    const int m = c >> 4, q = c & 15;
                    cp_async16(abase + (uint32_t)m * ROWB + (uint32_t)q * 16,
                               (const char*)g_ps_bf + ((size_t)((nby << 7) + m) << 8) + ((size_t)q << 4));
                }
                if (tid < 64)
                    cp_async16(sbase + NSBS_OFF + (uint32_t)tid * 16,
                               (const char*)g_nsbs + ((size_t)nby << 10) + ((size_t)tid << 4));
                cp_commit();
            }

            by = nby; bx = nbx; s ^= 1; slot = nslot;
        }
    }

#pragma unroll
    for (int o = 16; o; o >>= 1) nls += __shfl_xor_sync(0xffffffffu, nls, o);
    if (lane == 0) warpsum[wid] = nls;
    __syncthreads();
    if (tid == 0) {
        float sum = 0.f;
#pragma unroll
        for (int w = 0; w < 8; w++) sum += warpsum[w];
        atomicAdd(&g_acc[1], (double)sum);
    }
}

__global__ void k_final(float* out) {
    out[0] = (float)(g_acc[1] - g_acc[0]);   // -(link - nonlink)
}

extern "C" void kernel_launch(void* const* d_in, const int* in_sizes, int n_in,
                              void* d_out, int out_size) {
    const int*   edges   = (const int*)d_in[0];
    const int*   nps     = (const int*)d_in[1];   // nodes_p_star
    const int*   npp     = (const int*)d_in[2];   // nodes_p
    const float* beta_p  = (const float*)d_in[3];
    const float* beta_ps = (const float*)d_in[4];
    const float* p       = (const float*)d_in[5];
    const float* pstar   = (const float*)d_in[6];
    float* out = (float*)d_out;
    int E = in_sizes[0] / 2;

    // one-time side stream + events (no device memory involved)
    static cudaStream_t s2 = nullptr;
    static cudaEvent_t e_fork = nullptr, e_join = nullptr;
    if (s2 == nullptr) {
        cudaStreamCreateWithFlags(&s2, cudaStreamNonBlocking);
        cudaEventCreateWithFlags(&e_fork, cudaEventDisableTiming);
        cudaEventCreateWithFlags(&e_join, cudaEventDisableTiming);
    }

    cudaFuncSetAttribute(k_nonlink_mma, cudaFuncAttributeMaxDynamicSharedMemorySize, DYN_SMEM_NL);

    k_prep<<<(2 * NN + 7) / 8, 256>>>(p, pstar);
    k_gather<<<NB / 8, 256>>>(nps, npp, beta_p, beta_ps);

    // fork: link runs on a parallel graph branch, co-resident with the GEMM
    cudaEventRecord(e_fork, 0);
    cudaStreamWaitEvent(s2, e_fork, 0);
    k_link<<<2048, 256, 0, s2>>>(edges, E, beta_p, beta_ps);
    cudaEventRecord(e_join, s2);

    k_nonlink_mma<<<GRID_NL, 256, DYN_SMEM_NL>>>();

    // join: final combine waits on both branches
    cudaStreamWaitEvent(0, e_join, 0);
    k_final<<<1, 1>>>(out);
}

// round 17
// speedup vs baseline: 1.5997x; 1.0085x over previous
#include <cuda_runtime.h>
#include <cuda_bf16.h>
#include <cstdint>

#define DIMN 128
#define NB   16384
#define NN   20000
#define NTX  256                        // 64-wide col tiles
#define NTILES2 16512                   // sum over by of (256 - 2*by)
#define EPSL 1e-6f
#define L2E  1.4426950408889634f
#define GRID_NL 444                     // 3 CTAs per SM
#define CHUNK ((NTILES2 + GRID_NL - 1) / GRID_NL)   // 38
#define LINK_GRID 4096                  // 128-thread CTAs (fit 4K-reg residue per SM)

// smem geometry: rows padded to 272 B (136 bf16)
#define ROWB 272
#define TILEB_A (128 * ROWB)            // 34816
#define TILEB_B (64 * ROWB)             // 17408
#define RING_OFF (TILEB_A + 2 * TILEB_B)        // 69632; 3 x 512B npbp slices
#define NSBS_OFF (RING_OFF + 3 * 512)           // 71168; 1KB nsbs row slice
#define DYN_SMEM_NL (NSBS_OFF + 1024)           // 72192 B -> 3 CTAs/SM

// ---- scratch (static device globals; no allocation) ----
__device__ __align__(16) __nv_bfloat16 g_p_bf[NN * DIMN];     // full p table, bf16
__device__ __align__(16) __nv_bfloat16 g_pstar_bf[NN * DIMN]; // full p_star table, bf16
__device__ __align__(16) __nv_bfloat16 g_ps_bf[NB * DIMN];    // L2E * p_star[nodes_p_star]
__device__ __align__(16) __nv_bfloat16 g_pp_bf[NB * DIMN];    // L2E * p[nodes_p]
__device__ float2   g_nsbs[NB];        // {|scaled ps row|^2, L2E*beta_p_star}
__device__ float2   g_npbp[NB];        // {|scaled pp row|^2, L2E*beta_p}
__device__ double   g_acc[2];          // [0]=link, [1]=nonlink

static __device__ __forceinline__ float sqrt_approx(float x) {
    float r; asm("sqrt.approx.f32 %0, %1;" : "=f"(r) : "f"(x)); return r;
}
static __device__ __forceinline__ float ex2_approx(float x) {
    float r; asm("ex2.approx.f32 %0, %1;" : "=f"(r) : "f"(x)); return r;
}
static __device__ __forceinline__ uint32_t smem_u32(const void* p) {
    uint32_t a;
    asm("{ .reg .u64 t; cvta.to.shared.u64 t, %1; cvt.u32.u64 %0, t; }" : "=r"(a) : "l"(p));
    return a;
}
static __device__ __forceinline__ void cp_async16(uint32_t dst, const void* src) {
    asm volatile("cp.async.cg.shared.global [%0], [%1], 16;" :: "r"(dst), "l"(src) : "memory");
}
static __device__ __forceinline__ void cp_commit() {
    asm volatile("cp.async.commit_group;" ::: "memory");
}
template <int N> static __device__ __forceinline__ void cp_wait() {
    asm volatile("cp.async.wait_group %0;" :: "n"(N) : "memory");
}
static __device__ __forceinline__ void ldsm_x4(uint32_t& r0, uint32_t& r1,
                                               uint32_t& r2, uint32_t& r3, uint32_t a) {
    asm volatile("ldmatrix.sync.aligned.m8n8.x4.shared.b16 {%0,%1,%2,%3}, [%4];"
                 : "=r"(r0), "=r"(r1), "=r"(r2), "=r"(r3) : "r"(a));
}
static __device__ __forceinline__ void mma16816(float* d, const uint32_t* a,
                                                uint32_t b0, uint32_t b1) {
    asm volatile("mma.sync.aligned.m16n8k16.row.col.f32.bf16.bf16.f32 "
                 "{%0,%1,%2,%3}, {%4,%5,%6,%7}, {%8,%9}, {%0,%1,%2,%3};"
                 : "+f"(d[0]), "+f"(d[1]), "+f"(d[2]), "+f"(d[3])
                 : "r"(a[0]), "r"(a[1]), "r"(a[2]), "r"(a[3]), "r"(b0), "r"(b1));
}
static __device__ __forceinline__ float2 bf2f(uint32_t u) {
    __nv_bfloat162 h = *reinterpret_cast<__nv_bfloat162*>(&u);
    return __bfloat1622float2(h);
}

// One epilogue slice: 4 elements (rows r_lo, r_lo+8 x cols c0, c0+1).
// cv pairs come from an smem-staged slice (LDS).
static __device__ __forceinline__ void epi_slice(
    float& nls, const float* d, const float2 rv0, const float2 rv1,
    const float2* cvp, bool diag, int r_lo, int c0) {
    const float2 cv0 = cvp[0];
    const float2 cv1 = cvp[1];
    if (!diag) {
        nls += ex2_approx(rv0.y + cv0.y - sqrt_approx(fmaxf(rv0.x + cv0.x - 2.f * d[0], 0.f)));
        nls += ex2_approx(rv0.y + cv1.y - sqrt_approx(fmaxf(rv0.x + cv1.x - 2.f * d[1], 0.f)));
        nls += ex2_approx(rv1.y + cv0.y - sqrt_approx(fmaxf(rv1.x + cv0.x - 2.f * d[2], 0.f)));
        nls += ex2_approx(rv1.y + cv1.y - sqrt_approx(fmaxf(rv1.x + cv1.x - 2.f * d[3], 0.f)));
    } else {
        float w;
        w = ex2_approx(rv0.y + cv0.y - sqrt_approx(fmaxf(rv0.x + cv0.x - 2.f * d[0], 0.f)));
        if (r_lo < c0) nls += w;
        w = ex2_approx(rv0.y + cv1.y - sqrt_approx(fmaxf(rv0.x + cv1.x - 2.f * d[1], 0.f)));
        if (r_lo < c0 + 1) nls += w;
        w = ex2_approx(rv1.y + cv0.y - sqrt_approx(fmaxf(rv1.x + cv0.x - 2.f * d[2], 0.f)));
        if (r_lo + 8 < c0) nls += w;
        w = ex2_approx(rv1.y + cv1.y - sqrt_approx(fmaxf(rv1.x + cv1.x - 2.f * d[3], 0.f)));
        if (r_lo + 8 < c0 + 1) nls += w;
    }
}

// ---------------- kernels ----------------
// convert full p / p_star tables to bf16 (one warp per row per table); zero counters
__global__ void k_prep(const float* __restrict__ p, const float* __restrict__ pstar) {
    if (blockIdx.x == 0 && threadIdx.x == 0) { g_acc[0] = 0.0; g_acc[1] = 0.0; }
    int w    = blockIdx.x * 8 + (threadIdx.x >> 5);
    int lane = threadIdx.x & 31;
    int row  = w >> 1;
    if (row >= NN) return;
    const float* src = (w & 1) ? pstar : p;
    __nv_bfloat16* dst = (w & 1) ? g_pstar_bf : g_p_bf;
    float4 v = ((const float4*)(src + (size_t)row * DIMN))[lane];
    __nv_bfloat162* d = (__nv_bfloat162*)(dst + (size_t)row * DIMN);
    d[2 * lane + 0] = __floats2bfloat162_rn(v.x, v.y);
    d[2 * lane + 1] = __floats2bfloat162_rn(v.z, v.w);
}

// gather rows (from bf16 tables), scale by L2E, store scaled bf16 + {norm,beta} pairs
__global__ void k_gather(const int* __restrict__ nps, const int* __restrict__ npp,
                         const float* __restrict__ beta_p, const float* __restrict__ beta_ps) {
    int row  = blockIdx.x * 8 + (threadIdx.x >> 5);
    int lane = threadIdx.x & 31;
    if (row >= NB) return;
    int is = nps[row], ip = npp[row];
    uint2 rs = ((const uint2*)(g_pstar_bf + (size_t)is * DIMN))[lane];
    uint2 rp = ((const uint2*)(g_p_bf     + (size_t)ip * DIMN))[lane];

    float2 s0 = bf2f(rs.x), s1 = bf2f(rs.y), p0 = bf2f(rp.x), p1 = bf2f(rp.y);
    __nv_bfloat162 os0 = __floats2bfloat162_rn(s0.x * L2E, s0.y * L2E);
    __nv_bfloat162 os1 = __floats2bfloat162_rn(s1.x * L2E, s1.y * L2E);
    __nv_bfloat162 op0 = __floats2bfloat162_rn(p0.x * L2E, p0.y * L2E);
    __nv_bfloat162 op1 = __floats2bfloat162_rn(p1.x * L2E, p1.y * L2E);
    ((__nv_bfloat162*)(g_ps_bf + (size_t)row * DIMN))[2 * lane + 0] = os0;
    ((__nv_bfloat162*)(g_ps_bf + (size_t)row * DIMN))[2 * lane + 1] = os1;
    ((__nv_bfloat162*)(g_pp_bf + (size_t)row * DIMN))[2 * lane + 0] = op0;
    ((__nv_bfloat162*)(g_pp_bf + (size_t)row * DIMN))[2 * lane + 1] = op1;

    float2 a0 = __bfloat1622float2(os0), a1 = __bfloat1622float2(os1);
    float2 b0 = __bfloat1622float2(op0), b1 = __bfloat1622float2(op1);
    float a = a0.x*a0.x + a0.y*a0.y + a1.x*a1.x + a1.y*a1.y;
    float b = b0.x*b0.x + b0.y*b0.y + b1.x*b1.x + b1.y*b1.y;
#pragma unroll
    for (int o = 16; o; o >>= 1) {
        a += __shfl_xor_sync(0xffffffffu, a, o);
        b += __shfl_xor_sync(0xffffffffu, b, o);
    }
    if (lane == 0) {
        g_nsbs[row] = make_float2(a, beta_ps[is] * L2E);
        g_npbp[row] = make_float2(b, beta_p[ip] * L2E);
    }
}

// Link term: 128-thread CTAs (4 warps, 32 regs -> 4K regs/CTA) so one link CTA
// fits the register residue left by 3 nonlink CTAs per SM and truly co-resides.
// 8 lanes per edge, 4 edges per warp (3-deep shfl reduce).
__global__ __launch_bounds__(128)
void k_link(const int* __restrict__ edges, int E,
            const float* __restrict__ beta_p, const float* __restrict__ beta_ps) {
    __shared__ float wsum[4];
    const int gw   = (blockIdx.x * blockDim.x + threadIdx.x) >> 5;
    const int wid  = threadIdx.x >> 5;
    const int lane = threadIdx.x & 31;
    const int nw   = (gridDim.x * blockDim.x) >> 5;
    const int sub  = lane & 7;
    const int eq   = lane >> 3;

    float local = 0.f;
    for (int base = gw * 4; base < E; base += nw * 4) {
        const int e = base + eq;
        const bool valid = (e < E);
        float s = 0.f;
        int e0 = 0, e1 = 0;
        if (valid) {
            e0 = edges[e]; e1 = edges[E + e];
            const uint4* ra = (const uint4*)(g_p_bf     + (size_t)e0 * DIMN);
            const uint4* rb = (const uint4*)(g_pstar_bf + (size_t)e1 * DIMN);
            const uint4 a0 = ra[2 * sub], a1 = ra[2 * sub + 1];
            const uint4 b0 = rb[2 * sub], b1 = rb[2 * sub + 1];
#pragma unroll
            for (int w = 0; w < 4; w++) {
                const float2 fa = bf2f((&a0.x)[w]), fb = bf2f((&b0.x)[w]);
                const float dx = fa.x - fb.x + EPSL, dy = fa.y - fb.y + EPSL;
                s += dx * dx + dy * dy;
            }
#pragma unroll
            for (int w = 0; w < 4; w++) {
                const float2 fa = bf2f((&a1.x)[w]), fb = bf2f((&b1.x)[w]);
                const float dx = fa.x - fb.x + EPSL, dy = fa.y - fb.y + EPSL;
                s += dx * dx + dy * dy;
            }
        }
        s += __shfl_xor_sync(0xffffffffu, s, 1);
        s += __shfl_xor_sync(0xffffffffu, s, 2);
        s += __shfl_xor_sync(0xffffffffu, s, 4);
        if (valid && sub == 0)
            local += beta_ps[e0] + beta_p[e1] - sqrt_approx(s);
    }
#pragma unroll
    for (int o = 16; o; o >>= 1) local += __shfl_xor_sync(0xffffffffu, local, o);
    if (lane == 0) wsum[wid] = local;
    __syncthreads();
    if (threadIdx.x == 0) {
        float s = 0.f;
#pragma unroll
        for (int w = 0; w < 4; w++) s += wsum[w];
        atomicAdd(&g_acc[0], (double)s);
    }
}

// Non-link: persistent mma.sync bf16 GEMM over 128x64 triu tiles, 3 CTAs/SM.
// 8 warps x 32x32 strips; A (128 rows) persists across same-row tiles;
// B (64 rows) double-buffered; epilogue vectors staged in smem (LDS only).
__global__ __launch_bounds__(256, 3)
void k_nonlink_mma() {
    extern __shared__ __align__(16) char smem[];
    __shared__ float warpsum[8];
    const int tid  = threadIdx.x;
    const int wid  = tid >> 5;
    const int lane = tid & 31;
    const uint32_t sbase = smem_u32(smem);
    const uint32_t abase = sbase;
    const uint32_t bst[2] = { sbase + TILEB_A, sbase + TILEB_A + TILEB_B };
    const float2* const s_ring = (const float2*)(smem + RING_OFF);   // 3 x 64 float2
    const float2* const s_ns   = (const float2*)(smem + NSBS_OFF);   // 128 float2

    const int row0w = (wid & 3) * 32;     // 4 M-strips of 32
    const int col0w = (wid >> 2) * 32;    // 2 N-strips of 32
    const uint32_t lm_off = (uint32_t)(lane & 15) * ROWB + (uint32_t)(lane >> 4) * 16;
    const int lq = 2 * (lane & 3);
    const int lr = lane >> 2;

    float nls = 0.f;

    const int t0 = blockIdx.x * CHUNK;
    const int t1 = (t0 + CHUNK < NTILES2) ? (t0 + CHUNK) : NTILES2;

    if (t0 < t1) {
        // decode t0 -> (by, bx): row by has NTX - 2*by tiles, bx in [2*by, NTX)
        int by = 0, rem = t0;
        while (rem >= NTX - 2 * by) { rem -= NTX - 2 * by; by++; }
        int bx = 2 * by + rem;
        int slot = 0;

        // prologue: A(by) + nsbs(by) + B(bx) + npbp(bx)
#pragma unroll
        for (int it = 0; it < 8; it++) {
            const int c = tid + (it << 8);
            const int m = c >> 4, q = c & 15;
            cp_async16(abase + (uint32_t)m * ROWB + (uint32_t)q * 16,
                       (const char*)g_ps_bf + ((size_t)((by << 7) + m) << 8) + ((size_t)q << 4));
        }
#pragma unroll
        for (int it = 0; it < 4; it++) {
            const int c = tid + (it << 8);
            const int m = c >> 4, q = c & 15;
            cp_async16(bst[0] + (uint32_t)m * ROWB + (uint32_t)q * 16,
                       (const char*)g_pp_bf + ((size_t)((bx << 6) + m) << 8) + ((size_t)q << 4));
        }
        if (tid < 32)
            cp_async16(sbase + RING_OFF + (uint32_t)tid * 16,
                       (const char*)g_npbp + ((size_t)bx << 9) + ((size_t)tid << 4));
        else if (tid < 96)
            cp_async16(sbase + NSBS_OFF + (uint32_t)(tid - 32) * 16,
                       (const char*)g_nsbs + ((size_t)by << 10) + ((size_t)(tid - 32) << 4));
        cp_commit();

        int s = 0;
        for (int t = t0; t < t1; t++) {
            int nbx = bx + 1, nby = by;
            if (nbx >= NTX) { nby = by + 1; nbx = 2 * nby; }
            const int nslot = (slot + 1 == 3) ? 0 : slot + 1;
            const bool have_next = (t + 1 < t1);

            if (have_next) {
#pragma unroll
                for (int it = 0; it < 4; it++) {
                    const int c = tid + (it << 8);
                    const int m = c >> 4, q = c & 15;
                    cp_async16(bst[1 - s] + (uint32_t)m * ROWB + (uint32_t)q * 16,
                               (const char*)g_pp_bf + ((size_t)((nbx << 6) + m) << 8) + ((size_t)q << 4));
                }
                if (tid < 32)
                    cp_async16(sbase + RING_OFF + (uint32_t)nslot * 512 + (uint32_t)tid * 16,
                               (const char*)g_npbp + ((size_t)nbx << 9) + ((size_t)tid << 4));
            }
            cp_commit();
            cp_wait<1>();
            __syncthreads();

            const uint32_t aw = abase  + (uint32_t)row0w * ROWB + lm_off;
            const uint32_t bw = bst[s] + (uint32_t)col0w * ROWB + lm_off;

            float acc[2][4][4];
#pragma unroll
            for (int mi = 0; mi < 2; mi++)
#pragma unroll
                for (int n = 0; n < 4; n++)
#pragma unroll
                    for (int v = 0; v < 4; v++) acc[mi][n][v] = 0.f;

#pragma unroll
            for (int k = 0; k < 8; k++) {
                uint32_t a[2][4], bf[2][4];
#pragma unroll
                for (int mi = 0; mi < 2; mi++)
                    ldsm_x4(a[mi][0], a[mi][1], a[mi][2], a[mi][3],
                            aw + (uint32_t)mi * 16 * ROWB + (uint32_t)k * 32);
#pragma unroll
                for (int nj = 0; nj < 2; nj++)
                    ldsm_x4(bf[nj][0], bf[nj][1], bf[nj][2], bf[nj][3],
                            bw + (uint32_t)nj * 16 * ROWB + (uint32_t)k * 32);
#pragma unroll
                for (int mi = 0; mi < 2; mi++)
#pragma unroll
                    for (int n = 0; n < 4; n++) {
                        const int nj = n >> 1;
                        if ((n & 1) == 0) mma16816(acc[mi][n], a[mi], bf[nj][0], bf[nj][2]);
                        else              mma16816(acc[mi][n], a[mi], bf[nj][1], bf[nj][3]);
                    }
            }

            // batched epilogue (LDS-staged vectors; values pre-scaled by L2E)
            {
                const int crl = (by << 7) + row0w + lr;
                float2 rv[4];
                rv[0] = s_ns[row0w + lr];      rv[1] = s_ns[row0w + lr + 8];
                rv[2] = s_ns[row0w + lr + 16]; rv[3] = s_ns[row0w + lr + 24];
                const float2* const cnp = s_ring + slot * 64;
                const int cb = (bx << 6) + col0w + lq;
                const bool diag = ((bx >> 1) == by);
#pragma unroll
                for (int mi = 0; mi < 2; mi++)
#pragma unroll
                    for (int n = 0; n < 4; n++)
                        epi_slice(nls, acc[mi][n], rv[mi * 2], rv[mi * 2 + 1],
                                  cnp + col0w + lq + n * 8, diag,
                                  crl + mi * 16, cb + n * 8);
            }
            __syncthreads();    // done with A, B stage s, ring slot, nsbs

            if (have_next && nby != by) {   // A + nsbs refill for next row
#pragma unroll
                for (int it = 0; it < 8; it++) {
                    const int c = tid + (it << 8);
                    const int m = c >> 4, q = c & 15;
                    cp_async16(abase + (uint32_t)m * ROWB + (uint32_t)q * 16,
                               (const char*)g_ps_bf + ((size_t)((nby << 7) + m) << 8) + ((size_t)q << 4));
                }
                if (tid < 64)
                    cp_async16(sbase + NSBS_OFF + (uint32_t)tid * 16,
                               (const char*)g_nsbs + ((size_t)nby << 10) + ((size_t)tid << 4));
                cp_commit();
            }

            by = nby; bx = nbx; s ^= 1; slot = nslot;
        }
    }

#pragma unroll
    for (int o = 16; o; o >>= 1) nls += __shfl_xor_sync(0xffffffffu, nls, o);
    if (lane == 0) warpsum[wid] = nls;
    __syncthreads();
    if (tid == 0) {
        float sum = 0.f;
#pragma unroll
        for (int w = 0; w < 8; w++) sum += warpsum[w];
        atomicAdd(&g_acc[1], (double)sum);
    }
}

__global__ void k_final(float* out) {
    out[0] = (float)(g_acc[1] - g_acc[0]);   // -(link - nonlink)
}

extern "C" void kernel_launch(void* const* d_in, const int* in_sizes, int n_in,
                              void* d_out, int out_size) {
    const int*   edges   = (const int*)d_in[0];
    const int*   nps     = (const int*)d_in[1];   // nodes_p_star
    const int*   npp     = (const int*)d_in[2];   // nodes_p
    const float* beta_p  = (const float*)d_in[3];
    const float* beta_ps = (const float*)d_in[4];
    const float* p       = (const float*)d_in[5];
    const float* pstar   = (const float*)d_in[6];
    float* out = (float*)d_out;
    int E = in_sizes[0] / 2;

    // one-time side stream + events (no device memory involved)
    static cudaStream_t s2 = nullptr;
    static cudaEvent_t e_fork = nullptr, e_join = nullptr;
    if (s2 == nullptr) {
        cudaStreamCreateWithFlags(&s2, cudaStreamNonBlocking);
        cudaEventCreateWithFlags(&e_fork, cudaEventDisableTiming);
        cudaEventCreateWithFlags(&e_join, cudaEventDisableTiming);
    }

    cudaFuncSetAttribute(k_nonlink_mma, cudaFuncAttributeMaxDynamicSharedMemorySize, DYN_SMEM_NL);

    k_prep<<<(2 * NN + 7) / 8, 256>>>(p, pstar);
    k_gather<<<NB / 8, 256>>>(nps, npp, beta_p, beta_ps);

    // fork: link runs on a parallel graph branch, co-resident with the GEMM
    cudaEventRecord(e_fork, 0);
    cudaStreamWaitEvent(s2, e_fork, 0);
    k_link<<<LINK_GRID, 128, 0, s2>>>(edges, E, beta_p, beta_ps);
    cudaEventRecord(e_join, s2);

    k_nonlink_mma<<<GRID_NL, 256, DYN_SMEM_NL>>>();

    // join: final combine waits on both branches
    cudaStreamWaitEvent(0, e_join, 0);
    k_final<<<1, 1>>>(out);
}